// round 15
// baseline (speedup 1.0000x reference)
#include <cuda_runtime.h>
#include <cuda_fp16.h>
#include <cstdint>

#define N_NODES 8192
#define IN_F    512
#define OUT_F   128
#define SPLITJ  2
#define NCHUNK  ((N_NODES / SPLITJ) / 64)   // 64
#define LOG2E   1.44269504f

// ---------------- scratch (device globals: no allocation allowed) -------------
__device__ float  g_p[N_NODES];
__device__ float  g_q[N_NODES];
__device__ __half g_hT[(size_t)OUT_F * N_NODES];               // 2 MB  h^T fp16
__device__ float  g_acc[(size_t)SPLITJ * N_NODES * OUT_F];     // 8 MB
__device__ float  g_den[SPLITJ * N_NODES];

// ============================ helpers =========================================
__device__ __forceinline__ uint32_t smem_u32_of(const void* p) {
    uint32_t a;
    asm("{ .reg .u64 t; cvta.to.shared.u64 t, %1; cvt.u32.u64 %0, t; }"
        : "=r"(a) : "l"(p));
    return a;
}
__device__ __forceinline__ float ex2f(float x) {
    float r; asm("ex2.approx.f32 %0, %1;" : "=f"(r) : "f"(x)); return r;
}
__device__ __forceinline__ uint32_t pack_f16x2(float lo, float hi) {
    uint32_t r; asm("cvt.rn.f16x2.f32 %0, %1, %2;" : "=r"(r) : "f"(hi), "f"(lo));
    return r;
}
__device__ __forceinline__ uint32_t pk2(__half a, __half b) {
    return (uint32_t)__half_as_ushort(a) | ((uint32_t)__half_as_ushort(b) << 16);
}
__device__ __forceinline__ void sts128(uint32_t a, uint4 v) {
    asm volatile("st.shared.v4.b32 [%0], {%1,%2,%3,%4};"
                 :: "r"(a), "r"(v.x), "r"(v.y), "r"(v.z), "r"(v.w));
}
__device__ __forceinline__ float4 lds128f(uint32_t a) {
    float4 v;
    asm volatile("ld.shared.v4.f32 {%0,%1,%2,%3}, [%4];"
                 : "=f"(v.x), "=f"(v.y), "=f"(v.z), "=f"(v.w) : "r"(a));
    return v;
}
__device__ __forceinline__ void stsf(uint32_t a, float v) {
    asm volatile("st.shared.f32 [%0], %1;" :: "r"(a), "f"(v));
}
#define CPA16(dst, src) \
    asm volatile("cp.async.cg.shared.global [%0], [%1], 16;" \
                 :: "r"(dst), "l"(src) : "memory")
#define CPA_COMMIT() asm volatile("cp.async.commit_group;" ::: "memory")
#define CPA_WAIT1()  asm volatile("cp.async.wait_group 1;" ::: "memory")
#define CPA_WAIT0()  asm volatile("cp.async.wait_group 0;" ::: "memory")

#define LDSM4(R, ADDR) \
    asm volatile("ldmatrix.sync.aligned.m8n8.x4.shared.b16 {%0,%1,%2,%3}, [%4];" \
                 : "=r"((R)[0]), "=r"((R)[1]), "=r"((R)[2]), "=r"((R)[3])        \
                 : "r"(ADDR))
#define MMA(C, A, B0, B1) \
    asm volatile("mma.sync.aligned.m16n8k16.row.col.f32.f16.f16.f32 "            \
                 "{%0,%1,%2,%3}, {%4,%5,%6,%7}, {%8,%9}, {%0,%1,%2,%3};"         \
                 : "+f"((C)[0]), "+f"((C)[1]), "+f"((C)[2]), "+f"((C)[3])        \
                 : "r"((A)[0]), "r"((A)[1]), "r"((A)[2]), "r"((A)[3]),           \
                   "r"(B0), "r"(B1))

// w = exp(sigmoid(p_i+q_j)) = exp(1/(1+a*b)); deg-4 poly for e^s on [0,1]
__device__ __forceinline__ float wpoly(float a, float b, int m) {
    float c = fmaf(a, b, 1.0f);
    float s; asm("rcp.approx.f32 %0, %1;" : "=f"(s) : "f"(c));
    float p = fmaf(0.069558f, s, 0.139972f);
    p = fmaf(p, s, 0.510039f);
    p = fmaf(p, s, 0.998663f);
    p = fmaf(p, s, 1.000035f);
    return (m != 0) ? p : 0.0f;
}

// ===== Kernel A: h = X @ W (fp32) + fused p/q + h^T fp16 emission =============
__global__ void __launch_bounds__(256) gemm_xw_kernel(const float* __restrict__ X,
                                                      const float* __restrict__ W,
                                                      const float* __restrict__ a1,
                                                      const float* __restrict__ a2) {
    __shared__ float Xs[16][64];
    __shared__ float Ws[16][128];
    __shared__ __half hs[64][132];
    const int tid = threadIdx.x;
    const int rg  = tid >> 5;
    const int cg  = tid & 31;
    const int row0 = blockIdx.x * 64;

    float acc[8][4];
#pragma unroll
    for (int r = 0; r < 8; r++)
#pragma unroll
        for (int c = 0; c < 4; c++) acc[r][c] = 0.f;

    for (int k0 = 0; k0 < IN_F; k0 += 16) {
        {
            int r  = tid >> 2;
            int kq = (tid & 3) << 2;
            float4 v = *(const float4*)&X[(size_t)(row0 + r) * IN_F + k0 + kq];
            Xs[kq + 0][r] = v.x;  Xs[kq + 1][r] = v.y;
            Xs[kq + 2][r] = v.z;  Xs[kq + 3][r] = v.w;
        }
#pragma unroll
        for (int u = 0; u < 2; u++) {
            int e  = tid + u * 256;
            int kr = e >> 5;
            int cc = (e & 31) << 2;
            *(float4*)&Ws[kr][cc] = *(const float4*)&W[(size_t)(k0 + kr) * OUT_F + cc];
        }
        __syncthreads();
#pragma unroll
        for (int kk = 0; kk < 16; kk++) {
            float4 b = *(const float4*)&Ws[kk][cg << 2];
            float a8[8];
            *(float4*)&a8[0] = *(const float4*)&Xs[kk][rg * 8];
            *(float4*)&a8[4] = *(const float4*)&Xs[kk][rg * 8 + 4];
#pragma unroll
            for (int r = 0; r < 8; r++) {
                acc[r][0] += a8[r] * b.x;  acc[r][1] += a8[r] * b.y;
                acc[r][2] += a8[r] * b.z;  acc[r][3] += a8[r] * b.w;
            }
        }
        __syncthreads();
    }

    // ---- fused p/q: warp (rg) reduces over its 32 lanes (covering 128 cols) ----
    float4 av1 = *(const float4*)&a1[cg << 2];
    float4 av2 = *(const float4*)&a2[cg << 2];
#pragma unroll
    for (int r = 0; r < 8; r++) {
        float s1 = acc[r][0] * av1.x + acc[r][1] * av1.y +
                   acc[r][2] * av1.z + acc[r][3] * av1.w;
        float s2 = acc[r][0] * av2.x + acc[r][1] * av2.y +
                   acc[r][2] * av2.z + acc[r][3] * av2.w;
#pragma unroll
        for (int o = 16; o; o >>= 1) {
            s1 += __shfl_xor_sync(0xffffffffu, s1, o);
            s2 += __shfl_xor_sync(0xffffffffu, s2, o);
        }
        if (cg == 0) {
            g_p[row0 + rg * 8 + r] = s1;
            g_q[row0 + rg * 8 + r] = s2;
        }
    }

    // ---- stage h fp16 to smem, then coalesced h^T writes ----
#pragma unroll
    for (int r = 0; r < 8; r++) {
        *(uint32_t*)&hs[rg * 8 + r][cg * 4]     = pack_f16x2(acc[r][0], acc[r][1]);
        *(uint32_t*)&hs[rg * 8 + r][cg * 4 + 2] = pack_f16x2(acc[r][2], acc[r][3]);
    }
    __syncthreads();
    {
        const int f  = tid >> 1;
        const int nh = (tid & 1) * 32;
        uint32_t buf[16];
#pragma unroll
        for (int k = 0; k < 16; ++k)
            buf[k] = pk2(hs[nh + 2 * k][f], hs[nh + 2 * k + 1][f]);
        uint4* dst = (uint4*)((char*)g_hT + ((size_t)f * N_NODES + row0 + nh) * 2);
        dst[0] = make_uint4(buf[0],  buf[1],  buf[2],  buf[3]);
        dst[1] = make_uint4(buf[4],  buf[5],  buf[6],  buf[7]);
        dst[2] = make_uint4(buf[8],  buf[9],  buf[10], buf[11]);
        dst[3] = make_uint4(buf[12], buf[13], buf[14], buf[15]);
    }
}

// ======================= Kernel C: cp.async-pipelined fused attention =========
// grid (64, SPLITJ), 768 thr. Warps 0-7 producers (adj in registers, 1-chunk
// lookahead), 8-23 consumers (32x32 mma tiles). B double/triple buffered.
// smem: A[2] w fp16 128x(144B) | B ring[3] h^T fp16 128x(144B) | bq[4096] f32
#define ABASE(b)  ((uint32_t)(b) * 18432u)
#define BBASE(s)  (36864u + (uint32_t)(s) * 18432u)
#define QBASE     92160u
#define SMEM_ATTN 108544u

// producers (tid 0..255): cp.async B tile of chunk cc into ring slot
#define ISSUE(cc) do {                                                           \
    const int slot_ = (cc) % 3;                                                  \
    const int j0_   = jstart + (cc) * 64;                                        \
    _Pragma("unroll")                                                            \
    for (int u = 0; u < 4; ++u) {                                                \
        int e = tid + u * 256;                                                   \
        int row = e >> 3, seg = e & 7;                                           \
        uint32_t dst = sb + BBASE(slot_) + (uint32_t)(row * 144 + seg * 16);     \
        const char* src = (const char*)g_hT + ((size_t)row * N_NODES + j0_) * 2  \
                          + seg * 16;                                            \
        CPA16(dst, src);                                                         \
    }                                                                            \
    CPA_COMMIT();                                                                \
} while (0)

// producers: fire LDGs of adj chunk cc into registers m[4][2]
#define LOADADJ(cc) do {                                                         \
    const char* ap_ = (const char*)(adj + (size_t)(i0 + rbase) * N_NODES +       \
                                    jstart + (cc) * 64 + jo);                    \
    _Pragma("unroll")                                                            \
    for (int u = 0; u < 4; ++u) {                                                \
        m[u][0] = *(const int4*)(ap_ + (size_t)u * 32 * N_NODES * 4);            \
        m[u][1] = *(const int4*)(ap_ + (size_t)u * 32 * N_NODES * 4 + 16);       \
    }                                                                            \
} while (0)

// producers: weights of chunk cc (adj already in m) -> A[(cc)&1]
#define WEIGHT(cc) do {                                                          \
    const uint32_t ab_ = sb + ABASE((cc) & 1);                                   \
    float4 b0 = lds128f(sb + QBASE + (uint32_t)(((cc) * 64 + jo) * 4));          \
    float4 b1 = lds128f(sb + QBASE + (uint32_t)(((cc) * 64 + jo) * 4 + 16));     \
    _Pragma("unroll")                                                            \
    for (int u = 0; u < 4; ++u) {                                                \
        int4 m0 = m[u][0];                                                       \
        int4 m1 = m[u][1];                                                       \
        float w0 = wpoly(a8[u], b0.x, m0.x), w1 = wpoly(a8[u], b0.y, m0.y);      \
        float w2 = wpoly(a8[u], b0.z, m0.z), w3 = wpoly(a8[u], b0.w, m0.w);      \
        float w4 = wpoly(a8[u], b1.x, m1.x), w5 = wpoly(a8[u], b1.y, m1.y);      \
        float w6 = wpoly(a8[u], b1.z, m1.z), w7 = wpoly(a8[u], b1.w, m1.w);      \
        dsum[u] += ((w0 + w1) + (w2 + w3)) + ((w4 + w5) + (w6 + w7));            \
        uint4 pw = make_uint4(pack_f16x2(w0, w1), pack_f16x2(w2, w3),            \
                              pack_f16x2(w4, w5), pack_f16x2(w6, w7));           \
        sts128(ab_ + (uint32_t)((rbase + 32 * u) * 144 + jo * 2), pw);           \
    }                                                                            \
} while (0)

__global__ void __launch_bounds__(768, 1) attn_kernel(const int* __restrict__ adj) {
    extern __shared__ __align__(16) char smem[];
    const uint32_t sb = smem_u32_of(smem);
    const int tid  = threadIdx.x;
    const int lane = tid & 31;
    const int wid  = tid >> 5;
    const int i0     = blockIdx.x * 128;
    const int jstart = blockIdx.y * (N_NODES / SPLITJ);

    // ---------- bq table: exp(-q_j) for this CTA's whole j range ----------
    for (int e = tid; e < N_NODES / SPLITJ; e += 768)
        stsf(sb + QBASE + (uint32_t)(e * 4), ex2f(-g_q[jstart + e] * LOG2E));

    // ---------- producer state (warps 0-7; tid 0..255) ----------
    const int rbase = tid >> 3;          // 0..31
    const int jo    = (tid & 7) * 8;     // 0..56
    float a8[4], dsum[4];
    int4 m[4][2];

    // ---------- consumer state (warps 8-23): 32 i x 32 col each ----------
    float acc[2][4][4];
    const int cw  = wid - 8;             // 0..15
    const int iw0 = (cw & 3) * 32;
    const int nw0 = (cw >> 2) * 32;
    const uint32_t aThb = (uint32_t)((iw0 + (lane & 15)) * 144 + 16 * (lane >> 4));
    const uint32_t bThb = (uint32_t)(((nw0 + (lane & 7) + 8 * ((lane >> 4) & 1)) * 144) +
                                     16 * ((lane >> 3) & 1));

    if (wid < 8) {
#pragma unroll
        for (int u = 0; u < 4; ++u) {
            a8[u]   = ex2f(-g_p[i0 + rbase + 32 * u] * LOG2E);
            dsum[u] = 0.f;
        }
        LOADADJ(0);
        ISSUE(0);
        ISSUE(1);
        CPA_WAIT1();                     // B chunk 0 resident
    } else {
#pragma unroll
        for (int mt = 0; mt < 2; ++mt)
#pragma unroll
            for (int nt = 0; nt < 4; ++nt)
#pragma unroll
                for (int k = 0; k < 4; ++k) acc[mt][nt][k] = 0.f;
    }
    __syncthreads();                     // bq + B0 visible
    if (wid < 8) { WEIGHT(0); LOADADJ(1); }
    __syncthreads();                     // A0 ready

    for (int c = 0; c < NCHUNK; ++c) {
        if (wid < 8) {
            if (c + 2 < NCHUNK) { ISSUE(c + 2); CPA_WAIT1(); }
            else                { CPA_WAIT0(); }
            asm volatile("bar.sync 1, 256;" ::: "memory");   // producer-local
            if (c + 1 < NCHUNK) {
                WEIGHT(c + 1);                                // consumes m
                if (c + 2 < NCHUNK) LOADADJ(c + 2);           // refills m
            }
        } else {
            const uint32_t ab = sb + ABASE(c & 1) + aThb;
            const uint32_t bb = sb + BBASE(c % 3) + bThb;
#pragma unroll
            for (int ks = 0; ks < 4; ++ks) {
                uint32_t A0[4], A1[4];
                LDSM4(A0, ab + ks * 32);
                LDSM4(A1, ab + 2304 + ks * 32);
#pragma unroll
                for (int nt2 = 0; nt2 < 2; ++nt2) {
                    uint32_t B[4];
                    LDSM4(B, bb + nt2 * 2304 + ks * 32);
                    MMA(acc[0][2 * nt2],     A0, B[0], B[1]);
                    MMA(acc[0][2 * nt2 + 1], A0, B[2], B[3]);
                    MMA(acc[1][2 * nt2],     A1, B[0], B[1]);
                    MMA(acc[1][2 * nt2 + 1], A1, B[2], B[3]);
                }
            }
        }
        __syncthreads();
    }

    if (wid < 8) {
        // denominators: 8 lanes (same row) hold partial sums over j
#pragma unroll
        for (int u = 0; u < 4; ++u) {
            float v = dsum[u];
            v += __shfl_xor_sync(0xffffffffu, v, 1);
            v += __shfl_xor_sync(0xffffffffu, v, 2);
            v += __shfl_xor_sync(0xffffffffu, v, 4);
            if ((lane & 7) == 0)
                g_den[blockIdx.y * N_NODES + i0 + rbase + 32 * u] = v;
        }
    } else {
        const int r0 = lane >> 2;
        const int cp = (lane & 3) * 2;
#pragma unroll
        for (int mt = 0; mt < 2; ++mt)
#pragma unroll
            for (int nt = 0; nt < 4; ++nt) {
                int row = i0 + iw0 + 16 * mt + r0;
                int col = nw0 + 8 * nt + cp;
                size_t base = ((size_t)blockIdx.y * N_NODES + row) * OUT_F + col;
                *(float2*)&g_acc[base] = make_float2(acc[mt][nt][0], acc[mt][nt][1]);
                *(float2*)&g_acc[base + 8 * OUT_F] =
                    make_float2(acc[mt][nt][2], acc[mt][nt][3]);
            }
    }
}

// ======================= Kernel D: combine splits =============================
__global__ void __launch_bounds__(256) combine_kernel(float* __restrict__ out) {
    int e = blockIdx.x * blockDim.x + threadIdx.x;
    int i = e >> 5;
    int c = (e & 31) << 2;
    float4 s = make_float4(0.f, 0.f, 0.f, 0.f);
    float d = 0.f;
#pragma unroll
    for (int sp = 0; sp < SPLITJ; sp++) {
        float4 a = *(const float4*)&g_acc[((size_t)sp * N_NODES + i) * OUT_F + c];
        s.x += a.x; s.y += a.y; s.z += a.z; s.w += a.w;
        d += g_den[sp * N_NODES + i];
    }
    float inv = __fdividef(1.f, d);
    *(float4*)&out[(size_t)i * OUT_F + c] =
        make_float4(s.x * inv, s.y * inv, s.z * inv, s.w * inv);
}

// =============================================================================
extern "C" void kernel_launch(void* const* d_in, const int* in_sizes, int n_in,
                              void* d_out, int out_size) {
    const float* X   = (const float*)d_in[0];
    const int*   adj = (const int*)d_in[1];
    const float* W   = (const float*)d_in[2];
    const float* a1  = (const float*)d_in[3];
    const float* a2  = (const float*)d_in[4];
    float* out = (float*)d_out;

    cudaFuncSetAttribute(attn_kernel, cudaFuncAttributeMaxDynamicSharedMemorySize,
                         SMEM_ATTN);

    gemm_xw_kernel<<<N_NODES / 64, 256>>>(X, W, a1, a2);
    attn_kernel<<<dim3(N_NODES / 128, SPLITJ), 768, SMEM_ATTN>>>(adj);
    combine_kernel<<<(N_NODES * 32) / 256, 256>>>(out);
}